// round 6
// baseline (speedup 1.0000x reference)
#include <cuda_runtime.h>
#include <cstdint>
#include <cmath>

#define GH 512
#define GK 50
#define GT 1024
#define GB 128
#define BPP 52

// Packed fp32x2 FMA (sm_103a): acc = x * w + acc
#define FFMA2(acc, x, w) \
    asm("fma.rn.f32x2 %0, %1, %2, %0;" : "+l"(acc) : "l"(x), "l"(w))

// ---------------------------------------------------------------------------
// Fused persistent kernel: one CTA per batch element. 480 threads:
//   tid [0,256)   = GEMM producer (warps 0-7, LOW wid -> low arbiter priority)
//   tid [256,480) = Viterbi DP    (warps 8-14, HIGH wid -> issue priority)
// Producer computes feats rows t in blocks of 128 into a 256-step smem ring;
// DP (round-3 proven structure) consumes the ring. Cross-group sync via
// volatile smem block counters + threadfence_block; intra-group via named
// barriers (bar.sync 1,224 for DP; bar.sync 2,256 for producer).
// ---------------------------------------------------------------------------
// smem byte offsets
#define SM_WT    0                       // Wt[512][52] floats = 106496
#define SM_RING  106496                  // ring[256][52] floats = 53248
#define SM_BP    159744                  // bp 1023*52 = 53196 (pad 53248)
#define SM_VBUF  212992                  // 2*64 floats = 512
#define SM_RED   213504                  // 64 floats = 256
#define SM_TAGS  213760                  // 1024 bytes
#define SM_BIAS  214784                  // 64 floats = 256
#define SM_CNT   215040                  // counters (prod, cons)
#define SM_TOTAL 215104

#define BAR_DP()   asm volatile("bar.sync 1, 224;" ::: "memory")
#define BAR_PROD() asm volatile("bar.sync 2, 256;" ::: "memory")

// Pairwise argmax tree (select-form). Adjacent pairs keep index-ordered
// subranges; strict '>' == jnp.argmax first-max tie-breaking.
template <int Wd>
__device__ __forceinline__ void argmax_tree(float* val, int* id) {
    if constexpr (Wd > 1) {
        constexpr int P = Wd >> 1;
#pragma unroll
        for (int m = 0; m < P; m++) {
            bool g = val[2 * m + 1] > val[2 * m];
            val[m] = g ? val[2 * m + 1] : val[2 * m];
            id[m]  = g ? id[2 * m + 1]  : id[2 * m];
        }
        if constexpr (Wd & 1) { val[P] = val[Wd - 1]; id[P] = id[Wd - 1]; }
        argmax_tree<((Wd + 1) >> 1)>(val, id);
    }
}

__global__ __launch_bounds__(480, 1) void crf_fused_kernel(
    const float* __restrict__ hidden, const float* __restrict__ W,
    const float* __restrict__ bias, const float* __restrict__ trans,
    const float* __restrict__ startt, const float* __restrict__ stopt,
    float* __restrict__ out) {
    extern __shared__ char smem[];
    float* Wt   = reinterpret_cast<float*>(smem + SM_WT);
    float* ring = reinterpret_cast<float*>(smem + SM_RING);
    unsigned char* bp = reinterpret_cast<unsigned char*>(smem + SM_BP);
    float* vbuf = reinterpret_cast<float*>(smem + SM_VBUF);
    float* red  = reinterpret_cast<float*>(smem + SM_RED);
    unsigned char* tags = reinterpret_cast<unsigned char*>(smem + SM_TAGS);
    float* sbias = reinterpret_cast<float*>(smem + SM_BIAS);
    volatile int* pprod = reinterpret_cast<volatile int*>(smem + SM_CNT);
    volatile int* pcons = reinterpret_cast<volatile int*>(smem + SM_CNT + 8);

    const int b = blockIdx.x;
    const int tid = threadIdx.x;

    // ---- common setup (all 480 threads) ----
    // W transpose: W[k*512+h] -> Wt[h*52+k]
    for (int idx = tid; idx < GK * GH; idx += 480) {
        int k = idx >> 9;
        int h = idx & 511;
        Wt[h * 52 + k] = W[idx];
    }
    if (tid < GK) sbias[tid] = bias[tid];
    if (tid == 0) { *pprod = 0; *pcons = 0; }

    // DP-side private setup (before the global barrier)
    const int dtid = tid - 256;           // valid when tid >= 256
    const int j = dtid >> 2;              // 0..55
    const int r = dtid & 3;
    const int i0 = r * 13;
    float tr[13];
    if (tid >= 256) {
#pragma unroll
        for (int ii = 0; ii < 13; ii++) {
            int i = i0 + ii;
            tr[ii] = (j < GK && i < GK) ? trans[i * GK + j] : -INFINITY;
        }
        if (dtid >= GK && dtid < 64) { vbuf[dtid] = -INFINITY; vbuf[64 + dtid] = -INFINITY; }
    }

    __syncthreads();   // the only full-CTA barrier

    if (tid < 256) {
        // =================== PRODUCER: feats GEMM ===================
        const int prow  = tid >> 1;       // row within 128-row block
        const int khalf = tid & 1;        // k in [khalf*256, +256)
        const size_t hbase = ((size_t)b * GT) * GH + khalf * 256;

        for (int tb = 0; tb < 8; tb++) {
            if (tb >= 2) {                 // ring holds 2 blocks; backpressure
                while (*pcons < tb - 1) {}
                __threadfence_block();
            }
            const int trow = tb * 128 + prow;
            const float4* hx = reinterpret_cast<const float4*>(
                hidden + hbase + (size_t)trow * GH);

            unsigned long long acc[25];
#pragma unroll
            for (int p = 0; p < 25; p++) acc[p] = 0ull;

            float4 n0 = hx[0], n1 = hx[1];
            for (int k4 = 0; k4 < 64; k4++) {
                float4 cur = n0;
                n0 = n1;
                if (k4 < 62) n1 = hx[k4 + 2];
                const float* wbase = Wt + (khalf * 256 + k4 * 4) * 52;
#pragma unroll
                for (int u = 0; u < 4; u++) {
                    const float xv = (&cur.x)[u];
                    unsigned long long X;
                    asm("mov.b64 %0, {%1, %1};" : "=l"(X) : "r"(__float_as_uint(xv)));
                    const float* wr = wbase + u * 52;
#pragma unroll
                    for (int q = 0; q < 12; q++) {
                        ulonglong2 w = *reinterpret_cast<const ulonglong2*>(wr + q * 4);
                        FFMA2(acc[2 * q],     X, w.x);
                        FFMA2(acc[2 * q + 1], X, w.y);
                    }
                    unsigned long long wl = *reinterpret_cast<const unsigned long long*>(wr + 48);
                    FFMA2(acc[24], X, wl);
                }
            }

            // combine the two k-halves (adjacent lanes) + bias, store to ring
            float* dst = ring + (trow & 255) * 52;
#pragma unroll
            for (int p = 0; p < 25; p++) {
                float2 a = *reinterpret_cast<float2*>(&acc[p]);
                float ox = __shfl_xor_sync(0xffffffffu, a.x, 1);
                float oy = __shfl_xor_sync(0xffffffffu, a.y, 1);
                if (khalf == 0) {
                    float2 o;
                    o.x = a.x + ox + sbias[2 * p];
                    o.y = a.y + oy + sbias[2 * p + 1];
                    reinterpret_cast<float2*>(dst)[p] = o;
                }
            }

            BAR_PROD();                    // drains STS of all producers
            if (tid == 0) { __threadfence_block(); *pprod = tb + 1; }
        }
    } else {
        // =================== CONSUMER: Viterbi DP ===================
        // wait for feats block 0, then init v(t=0)
        while (*pprod < 1) {}
        __threadfence_block();
        if (r == 0 && j < GK) vbuf[j] = ring[j] + startt[j];
        BAR_DP();

        for (int t = 1; t < GT; t += 4) {
#pragma unroll
            for (int u = 0; u < 4; u++) {
                const int tt = t + u;
                if (tt < GT) {             // uniform across DP group
                    if ((tt & 127) == 0) { // entering a new feats block
                        while (*pprod < (tt >> 7) + 1) {}
                        __threadfence_block();
                    }
                    float feat = 0.f;
                    if (r == 1 && j < GK) feat = ring[(tt & 255) * 52 + j];

                    const float* vr = vbuf + (((tt - 1) & 1) << 6);
                    float cand[13];
                    int id[13];
#pragma unroll
                    for (int ii = 0; ii < 13; ii++) {
                        cand[ii] = vr[i0 + ii] + tr[ii];
                        id[ii] = i0 + ii;
                    }
                    argmax_tree<13>(cand, id);
                    float best = cand[0];
                    int bi = id[0];

                    float ov = __shfl_xor_sync(0xffffffffu, best, 1);
                    int   oi = __shfl_xor_sync(0xffffffffu, bi, 1);
                    bool g1 = (ov > best) || (ov == best && oi < bi);
                    best = g1 ? ov : best;
                    bi   = g1 ? oi : bi;
                    ov = __shfl_xor_sync(0xffffffffu, best, 2);
                    oi = __shfl_xor_sync(0xffffffffu, bi, 2);
                    bool g2 = (ov > best) || (ov == best && oi < bi);
                    best = g2 ? ov : best;
                    bi   = g2 ? oi : bi;

                    if (r == 1 && j < GK) {
                        vbuf[((tt & 1) << 6) + j] = feat + best;
                    } else if (r == 0 && j < GK) {
                        bp[(tt - 1) * BPP + j] = (unsigned char)bi;
                    }
                    BAR_DP();
                    // release feats block (tt>>7) once its last step is done
                    if (dtid == 0 && (tt & 127) == 127) {
                        __threadfence_block();
                        *pcons = (tt >> 7) + 1;
                    }
                }
            }
        }

        // final: v at t=1023 lives in buffer half 1
        if (r == 0 && j < GK) red[j] = vbuf[64 + j] + stopt[j];
        BAR_DP();

        if (dtid == 0) {
            float best = -INFINITY;
            int bj = 0;
            for (int k = 0; k < GK; k++) {
                float s = red[k];
                if (s > best) { best = s; bj = k; }
            }
            out[b] = best;
            int tag = bj;
            tags[GT - 1] = (unsigned char)tag;
            for (int k = GT - 2; k >= 0; k--) {
                tag = bp[k * BPP + tag];
                tags[k] = (unsigned char)tag;
            }
        }
        BAR_DP();

        float* tout = out + GB + (size_t)b * GT;
        for (int k = dtid; k < GT; k += 224) tout[k] = (float)tags[k];
    }
}

extern "C" void kernel_launch(void* const* d_in, const int* in_sizes, int n_in,
                              void* d_out, int out_size) {
    const float* hidden = (const float*)d_in[0];
    const float* W      = (const float*)d_in[1];
    const float* bias   = (const float*)d_in[2];
    const float* trans  = (const float*)d_in[3];
    const float* startt = (const float*)d_in[4];
    const float* stopt  = (const float*)d_in[5];
    float* out = (float*)d_out;

    cudaFuncSetAttribute(crf_fused_kernel,
                         cudaFuncAttributeMaxDynamicSharedMemorySize, SM_TOTAL);
    crf_fused_kernel<<<GB, 480, SM_TOTAL>>>(hidden, W, bias, trans,
                                            startt, stopt, out);
}

// round 7
// speedup vs baseline: 1.2593x; 1.2593x over previous
#include <cuda_runtime.h>
#include <cstdint>
#include <cmath>

#define GH 512
#define GK 50
#define GT 1024
#define GB 128
#define BPP 52

// Packed fp32x2 FMA (sm_103a): acc = x * w + acc
#define FFMA2(acc, x, w) \
    asm("fma.rn.f32x2 %0, %1, %2, %0;" : "+l"(acc) : "l"(x), "l"(w))

// ---------------------------------------------------------------------------
// Fused persistent kernel: one CTA per batch element. 480 threads:
//   tid [0,256)   = GEMM producer (warps 0-7, LOW wid -> low arbiter priority)
//   tid [256,480) = Viterbi DP    (warps 8-14, HIGH wid -> issue priority)
// Producer: warp-uniform n-half split (nh = wid&1), each thread computes ONE
// row x 25 outputs over the full K=512 serially -> 26 accumulator regs, no
// spills, and summation order identical to the proven standalone GEMM
// (rel_err was 0.0). Feats go t-blocks of 128 into a 256-step smem ring.
// DP: round-3 proven structure consuming the ring. Cross-group sync via
// volatile smem block counters; intra-group named barriers.
// ---------------------------------------------------------------------------
// smem byte offsets
#define SM_WT    0                       // Wt[512][52] floats = 106496
#define SM_RING  106496                  // ring[256][52] floats = 53248
#define SM_BP    159744                  // bp 1023*52 = 53196 (pad 53248)
#define SM_VBUF  212992                  // 2*64 floats = 512
#define SM_RED   213504                  // 64 floats = 256
#define SM_TAGS  213760                  // 1024 bytes
#define SM_BIAS  214784                  // 64 floats = 256
#define SM_CNT   215040                  // counters (prod, cons)
#define SM_TOTAL 215104

#define BAR_DP()   asm volatile("bar.sync 1, 224;" ::: "memory")
#define BAR_PROD() asm volatile("bar.sync 2, 256;" ::: "memory")

// Pairwise argmax tree (select-form). Adjacent pairs keep index-ordered
// subranges; strict '>' == jnp.argmax first-max tie-breaking.
template <int Wd>
__device__ __forceinline__ void argmax_tree(float* val, int* id) {
    if constexpr (Wd > 1) {
        constexpr int P = Wd >> 1;
#pragma unroll
        for (int m = 0; m < P; m++) {
            bool g = val[2 * m + 1] > val[2 * m];
            val[m] = g ? val[2 * m + 1] : val[2 * m];
            id[m]  = g ? id[2 * m + 1]  : id[2 * m];
        }
        if constexpr (Wd & 1) { val[P] = val[Wd - 1]; id[P] = id[Wd - 1]; }
        argmax_tree<((Wd + 1) >> 1)>(val, id);
    }
}

__global__ __launch_bounds__(480, 1) void crf_fused_kernel(
    const float* __restrict__ hidden, const float* __restrict__ W,
    const float* __restrict__ bias, const float* __restrict__ trans,
    const float* __restrict__ startt, const float* __restrict__ stopt,
    float* __restrict__ out) {
    extern __shared__ char smem[];
    float* Wt   = reinterpret_cast<float*>(smem + SM_WT);
    float* ring = reinterpret_cast<float*>(smem + SM_RING);
    unsigned char* bp = reinterpret_cast<unsigned char*>(smem + SM_BP);
    float* vbuf = reinterpret_cast<float*>(smem + SM_VBUF);
    float* red  = reinterpret_cast<float*>(smem + SM_RED);
    unsigned char* tags = reinterpret_cast<unsigned char*>(smem + SM_TAGS);
    float* sbias = reinterpret_cast<float*>(smem + SM_BIAS);
    volatile int* pprod = reinterpret_cast<volatile int*>(smem + SM_CNT);
    volatile int* pcons = reinterpret_cast<volatile int*>(smem + SM_CNT + 8);

    const int b = blockIdx.x;
    const int tid = threadIdx.x;

    // ---- common setup (all 480 threads) ----
    // W transpose: W[k*512+h] -> Wt[h*52+k]
    for (int idx = tid; idx < GK * GH; idx += 480) {
        int k = idx >> 9;
        int h = idx & 511;
        Wt[h * 52 + k] = W[idx];
    }
    if (tid < GK) sbias[tid] = bias[tid];
    if (tid == 0) { *pprod = 0; *pcons = 0; }

    // DP-side private setup (before the global barrier)
    const int dtid = tid - 256;           // valid when tid >= 256
    const int j = dtid >> 2;              // 0..55
    const int r = dtid & 3;
    const int i0 = r * 13;
    float tr[13];
    if (tid >= 256) {
#pragma unroll
        for (int ii = 0; ii < 13; ii++) {
            int i = i0 + ii;
            tr[ii] = (j < GK && i < GK) ? trans[i * GK + j] : -INFINITY;
        }
        if (dtid >= GK && dtid < 64) { vbuf[dtid] = -INFINITY; vbuf[64 + dtid] = -INFINITY; }
    }

    __syncthreads();   // the only full-CTA barrier

    if (tid < 256) {
        // =================== PRODUCER: feats GEMM ===================
        // Warp-uniform n-split: nh = wid&1 selects outputs [nh*24, ...)
        //   nh=0 -> k outputs 0..23  (12 f32x2 pairs)
        //   nh=1 -> k outputs 24..49 (13 f32x2 pairs)
        // row = 32*(wid>>1) + lane  (0..127 per block)
        const int pw   = tid >> 5;
        const int lane = tid & 31;
        const int nh   = pw & 1;
        const int prow = ((pw >> 1) << 5) | lane;
        const int kbase = nh * 24;
        const size_t hbase = ((size_t)b * GT) * GH;

        for (int tb = 0; tb < 8; tb++) {
            if (tb >= 2) {                 // ring holds 2 blocks; backpressure
                while (*pcons < tb - 1) {}
                __threadfence_block();
            }
            const int trow = tb * 128 + prow;
            const float4* hx = reinterpret_cast<const float4*>(
                hidden + hbase + (size_t)trow * GH);

            unsigned long long acc[13];
#pragma unroll
            for (int p = 0; p < 13; p++) acc[p] = 0ull;

            float4 n0 = hx[0], n1 = hx[1];
            for (int k4 = 0; k4 < 128; k4++) {
                float4 cur = n0;
                n0 = n1;
                if (k4 < 126) n1 = hx[k4 + 2];
#pragma unroll
                for (int u = 0; u < 4; u++) {
                    const float xv = (&cur.x)[u];
                    unsigned long long X;
                    asm("mov.b64 %0, {%1, %1};" : "=l"(X) : "r"(__float_as_uint(xv)));
                    const float* wr = Wt + (k4 * 4 + u) * 52 + kbase;
#pragma unroll
                    for (int q = 0; q < 6; q++) {
                        ulonglong2 w = *reinterpret_cast<const ulonglong2*>(wr + q * 4);
                        FFMA2(acc[2 * q],     X, w.x);
                        FFMA2(acc[2 * q + 1], X, w.y);
                    }
                    if (nh) {   // warp-uniform branch
                        unsigned long long wl =
                            *reinterpret_cast<const unsigned long long*>(wr + 24);
                        FFMA2(acc[12], X, wl);
                    }
                }
            }

            // bias + store this thread's 25-26 outputs to the ring
            const int npairs = 12 + nh;
            float* dst = ring + (trow & 255) * 52 + kbase;
#pragma unroll
            for (int p = 0; p < 13; p++) {
                if (p < npairs) {
                    float2 a = *reinterpret_cast<float2*>(&acc[p]);
                    a.x += sbias[kbase + 2 * p];
                    a.y += sbias[kbase + 2 * p + 1];
                    reinterpret_cast<float2*>(dst)[p] = a;
                }
            }

            BAR_PROD();                    // drains STS of all producers
            if (tid == 0) { __threadfence_block(); *pprod = tb + 1; }
        }
    } else {
        // =================== CONSUMER: Viterbi DP ===================
        // wait for feats block 0, then init v(t=0)
        while (*pprod < 1) {}
        __threadfence_block();
        if (r == 0 && j < GK) vbuf[j] = ring[j] + startt[j];
        BAR_DP();

        for (int t = 1; t < GT; t += 4) {
#pragma unroll
            for (int u = 0; u < 4; u++) {
                const int tt = t + u;
                if (tt < GT) {             // uniform across DP group
                    if ((tt & 127) == 0) { // entering a new feats block
                        while (*pprod < (tt >> 7) + 1) {}
                        __threadfence_block();
                    }
                    float feat = 0.f;
                    if (r == 1 && j < GK) feat = ring[(tt & 255) * 52 + j];

                    const float* vr = vbuf + (((tt - 1) & 1) << 6);
                    float cand[13];
                    int id[13];
#pragma unroll
                    for (int ii = 0; ii < 13; ii++) {
                        cand[ii] = vr[i0 + ii] + tr[ii];
                        id[ii] = i0 + ii;
                    }
                    argmax_tree<13>(cand, id);
                    float best = cand[0];
                    int bi = id[0];

                    float ov = __shfl_xor_sync(0xffffffffu, best, 1);
                    int   oi = __shfl_xor_sync(0xffffffffu, bi, 1);
                    bool g1 = (ov > best) || (ov == best && oi < bi);
                    best = g1 ? ov : best;
                    bi   = g1 ? oi : bi;
                    ov = __shfl_xor_sync(0xffffffffu, best, 2);
                    oi = __shfl_xor_sync(0xffffffffu, bi, 2);
                    bool g2 = (ov > best) || (ov == best && oi < bi);
                    best = g2 ? ov : best;
                    bi   = g2 ? oi : bi;

                    if (r == 1 && j < GK) {
                        vbuf[((tt & 1) << 6) + j] = feat + best;
                    } else if (r == 0 && j < GK) {
                        bp[(tt - 1) * BPP + j] = (unsigned char)bi;
                    }
                    BAR_DP();
                    // release feats block (tt>>7) once its last step is done
                    if (dtid == 0 && (tt & 127) == 127) {
                        __threadfence_block();
                        *pcons = (tt >> 7) + 1;
                    }
                }
            }
        }

        // final: v at t=1023 lives in buffer half 1
        if (r == 0 && j < GK) red[j] = vbuf[64 + j] + stopt[j];
        BAR_DP();

        if (dtid == 0) {
            float best = -INFINITY;
            int bj = 0;
            for (int k = 0; k < GK; k++) {
                float s = red[k];
                if (s > best) { best = s; bj = k; }
            }
            out[b] = best;
            int tag = bj;
            tags[GT - 1] = (unsigned char)tag;
            for (int k = GT - 2; k >= 0; k--) {
                tag = bp[k * BPP + tag];
                tags[k] = (unsigned char)tag;
            }
        }
        BAR_DP();

        float* tout = out + GB + (size_t)b * GT;
        for (int k = dtid; k < GT; k += 224) tout[k] = (float)tags[k];
    }
}

extern "C" void kernel_launch(void* const* d_in, const int* in_sizes, int n_in,
                              void* d_out, int out_size) {
    const float* hidden = (const float*)d_in[0];
    const float* W      = (const float*)d_in[1];
    const float* bias   = (const float*)d_in[2];
    const float* trans  = (const float*)d_in[3];
    const float* startt = (const float*)d_in[4];
    const float* stopt  = (const float*)d_in[5];
    float* out = (float*)d_out;

    cudaFuncSetAttribute(crf_fused_kernel,
                         cudaFuncAttributeMaxDynamicSharedMemorySize, SM_TOTAL);
    crf_fused_kernel<<<GB, 480, SM_TOTAL>>>(hidden, W, bias, trans,
                                            startt, stopt, out);
}

// round 8
// speedup vs baseline: 1.2649x; 1.0044x over previous
#include <cuda_runtime.h>
#include <cstdint>
#include <cmath>

#define GH 512
#define GK 50
#define GT 1024
#define GB 128
#define BPP 52

// Packed fp32x2 FMA (sm_103a): acc = x * w + acc
#define FFMA2(acc, x, w) \
    asm("fma.rn.f32x2 %0, %1, %2, %0;" : "+l"(acc) : "l"(x), "l"(w))

// ---------------------------------------------------------------------------
// Fused persistent kernel: one CTA per batch element. 480 threads:
//   tid [0,256)   = GEMM producer (warps 0-7, LOW wid -> low arbiter priority)
//   tid [256,480) = Viterbi DP    (warps 8-14, HIGH wid -> issue priority)
// Producer: warp-uniform n-half split (nh = wid&1), each thread computes ONE
// row x ~25 outputs over the full K=512 serially -> no spills, summation
// order identical to the proven standalone GEMM (rel_err 0.0).
// Feats flow through a 256-step smem ring in 128-step blocks.
// DP: round-3 proven structure consuming the ring.
// ROUND-8 FIX: spin-waits use __nanosleep backoff. The previous tight
// volatile-LDS polls (256 threads, ~10us per block) saturated the LSU and
// inflated the DP chain's LDS latency ~78%.
// ---------------------------------------------------------------------------
// smem byte offsets
#define SM_WT    0                       // Wt[512][52] floats = 106496
#define SM_RING  106496                  // ring[256][52] floats = 53248
#define SM_BP    159744                  // bp 1023*52 = 53196 (pad 53248)
#define SM_VBUF  212992                  // 2*64 floats = 512
#define SM_RED   213504                  // 64 floats = 256
#define SM_TAGS  213760                  // 1024 bytes
#define SM_BIAS  214784                  // 64 floats = 256
#define SM_CNT   215040                  // counters (prod, cons)
#define SM_TOTAL 215104

#define BAR_DP()   asm volatile("bar.sync 1, 224;" ::: "memory")
#define BAR_PROD() asm volatile("bar.sync 2, 256;" ::: "memory")

// Pairwise argmax tree (select-form). Adjacent pairs keep index-ordered
// subranges; strict '>' == jnp.argmax first-max tie-breaking.
template <int Wd>
__device__ __forceinline__ void argmax_tree(float* val, int* id) {
    if constexpr (Wd > 1) {
        constexpr int P = Wd >> 1;
#pragma unroll
        for (int m = 0; m < P; m++) {
            bool g = val[2 * m + 1] > val[2 * m];
            val[m] = g ? val[2 * m + 1] : val[2 * m];
            id[m]  = g ? id[2 * m + 1]  : id[2 * m];
        }
        if constexpr (Wd & 1) { val[P] = val[Wd - 1]; id[P] = id[Wd - 1]; }
        argmax_tree<((Wd + 1) >> 1)>(val, id);
    }
}

__global__ __launch_bounds__(480, 1) void crf_fused_kernel(
    const float* __restrict__ hidden, const float* __restrict__ W,
    const float* __restrict__ bias, const float* __restrict__ trans,
    const float* __restrict__ startt, const float* __restrict__ stopt,
    float* __restrict__ out) {
    extern __shared__ char smem[];
    float* Wt   = reinterpret_cast<float*>(smem + SM_WT);
    float* ring = reinterpret_cast<float*>(smem + SM_RING);
    unsigned char* bp = reinterpret_cast<unsigned char*>(smem + SM_BP);
    float* vbuf = reinterpret_cast<float*>(smem + SM_VBUF);
    float* red  = reinterpret_cast<float*>(smem + SM_RED);
    unsigned char* tags = reinterpret_cast<unsigned char*>(smem + SM_TAGS);
    float* sbias = reinterpret_cast<float*>(smem + SM_BIAS);
    volatile int* pprod = reinterpret_cast<volatile int*>(smem + SM_CNT);
    volatile int* pcons = reinterpret_cast<volatile int*>(smem + SM_CNT + 8);

    const int b = blockIdx.x;
    const int tid = threadIdx.x;

    // ---- common setup (all 480 threads) ----
    // W transpose: W[k*512+h] -> Wt[h*52+k]
    for (int idx = tid; idx < GK * GH; idx += 480) {
        int k = idx >> 9;
        int h = idx & 511;
        Wt[h * 52 + k] = W[idx];
    }
    if (tid < GK) sbias[tid] = bias[tid];
    if (tid == 0) { *pprod = 0; *pcons = 0; }

    // DP-side private setup (before the global barrier)
    const int dtid = tid - 256;           // valid when tid >= 256
    const int j = dtid >> 2;              // 0..55
    const int r = dtid & 3;
    const int i0 = r * 13;
    float tr[13];
    if (tid >= 256) {
#pragma unroll
        for (int ii = 0; ii < 13; ii++) {
            int i = i0 + ii;
            tr[ii] = (j < GK && i < GK) ? trans[i * GK + j] : -INFINITY;
        }
        if (dtid >= GK && dtid < 64) { vbuf[dtid] = -INFINITY; vbuf[64 + dtid] = -INFINITY; }
    }

    __syncthreads();   // the only full-CTA barrier

    if (tid < 256) {
        // =================== PRODUCER: feats GEMM ===================
        // Warp-uniform n-split: nh = wid&1 selects outputs [nh*24, ...)
        //   nh=0 -> k outputs 0..23  (12 f32x2 pairs)
        //   nh=1 -> k outputs 24..49 (13 f32x2 pairs)
        // row = 32*(wid>>1) + lane  (0..127 per block)
        const int pw   = tid >> 5;
        const int lane = tid & 31;
        const int nh   = pw & 1;
        const int prow = ((pw >> 1) << 5) | lane;
        const int kbase = nh * 24;
        const size_t hbase = ((size_t)b * GT) * GH;

        for (int tb = 0; tb < 8; tb++) {
            if (tb >= 2) {                 // ring holds 2 blocks; backpressure
                // BACKOFF poll: tight volatile-LDS spin here starved the DP
                // chain's LDS path. ~450-cycle sleep between polls.
                while (*pcons < tb - 1) { __nanosleep(256); }
                __threadfence_block();
            }
            const int trow = tb * 128 + prow;
            const float4* hx = reinterpret_cast<const float4*>(
                hidden + hbase + (size_t)trow * GH);

            unsigned long long acc[13];
#pragma unroll
            for (int p = 0; p < 13; p++) acc[p] = 0ull;

            float4 n0 = hx[0], n1 = hx[1];
            for (int k4 = 0; k4 < 128; k4++) {
                float4 cur = n0;
                n0 = n1;
                if (k4 < 126) n1 = hx[k4 + 2];
#pragma unroll
                for (int u = 0; u < 4; u++) {
                    const float xv = (&cur.x)[u];
                    unsigned long long X;
                    asm("mov.b64 %0, {%1, %1};" : "=l"(X) : "r"(__float_as_uint(xv)));
                    const float* wr = Wt + (k4 * 4 + u) * 52 + kbase;
#pragma unroll
                    for (int q = 0; q < 6; q++) {
                        ulonglong2 w = *reinterpret_cast<const ulonglong2*>(wr + q * 4);
                        FFMA2(acc[2 * q],     X, w.x);
                        FFMA2(acc[2 * q + 1], X, w.y);
                    }
                    if (nh) {   // warp-uniform branch
                        unsigned long long wl =
                            *reinterpret_cast<const unsigned long long*>(wr + 24);
                        FFMA2(acc[12], X, wl);
                    }
                }
            }

            // bias + store this thread's 24-26 outputs to the ring
            const int npairs = 12 + nh;
            float* dst = ring + (trow & 255) * 52 + kbase;
#pragma unroll
            for (int p = 0; p < 13; p++) {
                if (p < npairs) {
                    float2 a = *reinterpret_cast<float2*>(&acc[p]);
                    a.x += sbias[kbase + 2 * p];
                    a.y += sbias[kbase + 2 * p + 1];
                    reinterpret_cast<float2*>(dst)[p] = a;
                }
            }

            BAR_PROD();                    // drains STS of all producers
            if (tid == 0) { __threadfence_block(); *pprod = tb + 1; }
        }
    } else {
        // =================== CONSUMER: Viterbi DP ===================
        // wait for feats block 0, then init v(t=0)
        while (*pprod < 1) { __nanosleep(64); }
        __threadfence_block();
        if (r == 0 && j < GK) vbuf[j] = ring[j] + startt[j];
        BAR_DP();

        for (int t = 1; t < GT; t += 4) {
#pragma unroll
            for (int u = 0; u < 4; u++) {
                const int tt = t + u;
                if (tt < GT) {             // uniform across DP group
                    if ((tt & 127) == 0) { // entering a new feats block
                        // poll-first (usually satisfied), short backoff
                        if (*pprod < (tt >> 7) + 1) {
                            while (*pprod < (tt >> 7) + 1) { __nanosleep(64); }
                        }
                        __threadfence_block();
                    }
                    float feat = 0.f;
                    if (r == 1 && j < GK) feat = ring[(tt & 255) * 52 + j];

                    const float* vr = vbuf + (((tt - 1) & 1) << 6);
                    float cand[13];
                    int id[13];
#pragma unroll
                    for (int ii = 0; ii < 13; ii++) {
                        cand[ii] = vr[i0 + ii] + tr[ii];
                        id[ii] = i0 + ii;
                    }
                    argmax_tree<13>(cand, id);
                    float best = cand[0];
                    int bi = id[0];

                    float ov = __shfl_xor_sync(0xffffffffu, best, 1);
                    int   oi = __shfl_xor_sync(0xffffffffu, bi, 1);
                    bool g1 = (ov > best) || (ov == best && oi < bi);
                    best = g1 ? ov : best;
                    bi   = g1 ? oi : bi;
                    ov = __shfl_xor_sync(0xffffffffu, best, 2);
                    oi = __shfl_xor_sync(0xffffffffu, bi, 2);
                    bool g2 = (ov > best) || (ov == best && oi < bi);
                    best = g2 ? ov : best;
                    bi   = g2 ? oi : bi;

                    if (r == 1 && j < GK) {
                        vbuf[((tt & 1) << 6) + j] = feat + best;
                    } else if (r == 0 && j < GK) {
                        bp[(tt - 1) * BPP + j] = (unsigned char)bi;
                    }
                    BAR_DP();
                    // release feats block (tt>>7) once its last step is done
                    if (dtid == 0 && (tt & 127) == 127) {
                        __threadfence_block();
                        *pcons = (tt >> 7) + 1;
                    }
                }
            }
        }

        // final: v at t=1023 lives in buffer half 1
        if (r == 0 && j < GK) red[j] = vbuf[64 + j] + stopt[j];
        BAR_DP();

        if (dtid == 0) {
            float best = -INFINITY;
            int bj = 0;
            for (int k = 0; k < GK; k++) {
                float s = red[k];
                if (s > best) { best = s; bj = k; }
            }
            out[b] = best;
            int tag = bj;
            tags[GT - 1] = (unsigned char)tag;
            for (int k = GT - 2; k >= 0; k--) {
                tag = bp[k * BPP + tag];
                tags[k] = (unsigned char)tag;
            }
        }
        BAR_DP();

        float* tout = out + GB + (size_t)b * GT;
        for (int k = dtid; k < GT; k += 224) tout[k] = (float)tags[k];
    }
}

extern "C" void kernel_launch(void* const* d_in, const int* in_sizes, int n_in,
                              void* d_out, int out_size) {
    const float* hidden = (const float*)d_in[0];
    const float* W      = (const float*)d_in[1];
    const float* bias   = (const float*)d_in[2];
    const float* trans  = (const float*)d_in[3];
    const float* startt = (const float*)d_in[4];
    const float* stopt  = (const float*)d_in[5];
    float* out = (float*)d_out;

    cudaFuncSetAttribute(crf_fused_kernel,
                         cudaFuncAttributeMaxDynamicSharedMemorySize, SM_TOTAL);
    crf_fused_kernel<<<GB, 480, SM_TOTAL>>>(hidden, W, bias, trans,
                                            startt, stopt, out);
}